// round 1
// baseline (speedup 1.0000x reference)
#include <cuda_runtime.h>
#include <math.h>

#define S_TOK 4096
#define MDIM  1024
#define NEXP  8
#define CAP   1024
#define NSLOT (NEXP*CAP)        // 8192
#define GATE_BLOCKS (S_TOK/8)   // 512

// ---------------- device scratch (no allocations allowed) ----------------
__device__ int   g_e1[S_TOK], g_e2[S_TOK];
__device__ float g_p1[S_TOK], g_p2[S_TOK];
__device__ float g_w1[S_TOK], g_w2[S_TOK];
__device__ int   g_slot1[S_TOK], g_slot2[S_TOK];
__device__ int   g_slot2tok[NSLOT];
__device__ float g_me_part[GATE_BLOCKS*NEXP];
__device__ int   g_ce_part[GATE_BLOCKS*NEXP];
__device__ float g_disp[(size_t)NSLOT*MDIM];   // 32 MB
__device__ float g_eout[(size_t)NSLOT*MDIM];   // 32 MB

// ---------------- init: reset slot->token map ----------------
__global__ void k_init() {
    int i = blockIdx.x * blockDim.x + threadIdx.x;
    if (i < NSLOT) g_slot2tok[i] = -1;
}

// ---------------- gating: logits, softmax, top1/top2 ----------------
// 8 warps per block, 1 token per warp
__global__ void k_gate(const float* __restrict__ x, const float* __restrict__ wg) {
    int warp = threadIdx.x >> 5, lane = threadIdx.x & 31;
    int s = blockIdx.x * 8 + warp;

    float acc[NEXP];
#pragma unroll
    for (int e = 0; e < NEXP; e++) acc[e] = 0.f;

    const float* xr = x + (size_t)s * MDIM;
    for (int m = lane; m < MDIM; m += 32) {
        float xv = xr[m];
        const float4* w4 = (const float4*)(wg + (size_t)m * NEXP);
        float4 w0 = w4[0], w1 = w4[1];
        acc[0] += xv * w0.x; acc[1] += xv * w0.y;
        acc[2] += xv * w0.z; acc[3] += xv * w0.w;
        acc[4] += xv * w1.x; acc[5] += xv * w1.y;
        acc[6] += xv * w1.z; acc[7] += xv * w1.w;
    }
#pragma unroll
    for (int o = 16; o > 0; o >>= 1) {
#pragma unroll
        for (int e = 0; e < NEXP; e++)
            acc[e] += __shfl_down_sync(0xFFFFFFFFu, acc[e], o);
    }

    __shared__ float sh_g[8][NEXP];
    __shared__ int   sh_e1[8];

    if (lane == 0) {
        // softmax over logits acc[]
        float mx = acc[0];
#pragma unroll
        for (int e = 1; e < NEXP; e++) mx = fmaxf(mx, acc[e]);
        float ex[NEXP]; float sum = 0.f;
#pragma unroll
        for (int e = 0; e < NEXP; e++) { ex[e] = expf(acc[e] - mx); sum += ex[e]; }
        float inv = 1.f / sum;

        // top1 / top2 by logits (first-max wins, matches jnp.argmax)
        int e1 = 0; float b1 = acc[0];
#pragma unroll
        for (int e = 1; e < NEXP; e++) if (acc[e] > b1) { b1 = acc[e]; e1 = e; }
        int e2 = -1; float b2 = -3.4e38f;
#pragma unroll
        for (int e = 0; e < NEXP; e++) if (e != e1 && acc[e] > b2) { b2 = acc[e]; e2 = e; }

        float p1 = 0.f, p2 = 0.f;
#pragma unroll
        for (int e = 0; e < NEXP; e++) {
            float ge = ex[e] * inv;
            if (e == e1) p1 = ge;
            if (e == e2) p2 = ge;
            sh_g[warp][e] = ge;
        }
        g_e1[s] = e1; g_e2[s] = e2;
        g_p1[s] = p1; g_p2[s] = p2;
        sh_e1[warp] = e1;
    }
    __syncthreads();

    // deterministic per-block partials for l_aux
    if (threadIdx.x < NEXP) {
        int e = threadIdx.x;
        float ms = 0.f; int cs = 0;
#pragma unroll
        for (int w = 0; w < 8; w++) { ms += sh_g[w][e]; cs += (sh_e1[w] == e); }
        g_me_part[blockIdx.x * NEXP + e] = ms;
        g_ce_part[blockIdx.x * NEXP + e] = cs;
    }
}

// ---------------- scan: capacity positions, weights, slot map, l_aux ----------------
__global__ void k_scan(float* __restrict__ out, int out_size) {
    const int T = 256, PT = S_TOK / T;   // 16 tokens per thread
    int tid = threadIdx.x;

    __shared__ int   sc1[T][NEXP], sc2[T][NEXP];
    __shared__ float sh_me[NEXP];
    __shared__ int   sh_ce[NEXP];
    __shared__ int   tot1[NEXP];

    if (tid < NEXP) {
        float ms = 0.f; int cs = 0;
        for (int b = 0; b < GATE_BLOCKS; b++) {
            ms += g_me_part[b * NEXP + tid];
            cs += g_ce_part[b * NEXP + tid];
        }
        sh_me[tid] = ms; sh_ce[tid] = cs;
    }

    int c1[NEXP], c2[NEXP];
#pragma unroll
    for (int e = 0; e < NEXP; e++) { c1[e] = 0; c2[e] = 0; }
    for (int i = 0; i < PT; i++) {
        int s = tid * PT + i;
        c1[g_e1[s]]++;
        c2[g_e2[s]]++;
    }
#pragma unroll
    for (int e = 0; e < NEXP; e++) { sc1[tid][e] = c1[e]; sc2[tid][e] = c2[e]; }
    __syncthreads();

    // inclusive Hillis-Steele scan
    for (int off = 1; off < T; off *= 2) {
        int v1[NEXP], v2[NEXP];
        if (tid >= off) {
#pragma unroll
            for (int e = 0; e < NEXP; e++) { v1[e] = sc1[tid - off][e]; v2[e] = sc2[tid - off][e]; }
        }
        __syncthreads();
        if (tid >= off) {
#pragma unroll
            for (int e = 0; e < NEXP; e++) { sc1[tid][e] += v1[e]; sc2[tid][e] += v2[e]; }
        }
        __syncthreads();
    }
    if (tid < NEXP) tot1[tid] = sc1[T - 1][tid];

    int b1[NEXP], b2[NEXP];
#pragma unroll
    for (int e = 0; e < NEXP; e++) { b1[e] = sc1[tid][e] - c1[e]; b2[e] = sc2[tid][e] - c2[e]; }
    __syncthreads();

    for (int i = 0; i < PT; i++) {
        int s = tid * PT + i;
        int e1 = g_e1[s], e2 = g_e2[s];
        int loc1 = b1[e1]++;
        int loc2 = b2[e2]++ + tot1[e2];
        float p1 = g_p1[s], p2 = g_p2[s];
        bool k1 = (loc1 < CAP), k2 = (loc2 < CAP);
        float gg1 = k1 ? p1 : 0.f, gg2 = k2 ? p2 : 0.f;
        float den = gg1 + gg2;
        den = fmaxf(den, 1.1920929e-07f);
        g_w1[s] = gg1 / den;
        g_w2[s] = gg2 / den;
        int sl1 = k1 ? (e1 * CAP + loc1) : -1;
        int sl2 = k2 ? (e2 * CAP + loc2) : -1;
        g_slot1[s] = sl1; g_slot2[s] = sl2;
        if (sl1 >= 0) g_slot2tok[sl1] = s;
        if (sl2 >= 0) g_slot2tok[sl2] = s;
    }

    if (tid == 0 && out_size > S_TOK * MDIM) {
        float la = 0.f;
#pragma unroll
        for (int e = 0; e < NEXP; e++)
            la += (sh_me[e] / (float)S_TOK) * ((float)sh_ce[e] / (float)S_TOK);
        out[(size_t)S_TOK * MDIM] = la * (float)NEXP;
    }
}

// ---------------- gather: build per-expert token buffers ----------------
__global__ void k_gather(const float* __restrict__ x) {
    int slot = blockIdx.x;
    int t = g_slot2tok[slot];
    float4* dst = (float4*)(g_disp + (size_t)slot * MDIM);
    int i = threadIdx.x;   // 256 threads, MDIM/4 = 256
    if (t < 0) {
        dst[i] = make_float4(0.f, 0.f, 0.f, 0.f);
    } else {
        const float4* src = (const float4*)(x + (size_t)t * MDIM);
        dst[i] = src[i];
    }
}

// ---------------- per-expert GEMM: [CAP,M] @ [M,M] + bias ----------------
#define BM 128
#define BN 64
#define BK 16
#define TM 8
#define TN 4
__global__ void __launch_bounds__(256) k_gemm(const float* __restrict__ W,
                                              const float* __restrict__ bias) {
    __shared__ float As[BK][BM + 4];
    __shared__ float Bs[BK][BN];

    int e = blockIdx.z;
    const float* A  = g_disp + (size_t)e * CAP * MDIM;
    const float* Bw = W      + (size_t)e * MDIM * MDIM;
    float*       Cp = g_eout + (size_t)e * CAP * MDIM;

    int row0 = blockIdx.y * BM;
    int col0 = blockIdx.x * BN;
    int tid = threadIdx.x;
    int tx = tid & 15, ty = tid >> 4;

    float acc[TM][TN];
#pragma unroll
    for (int i = 0; i < TM; i++)
#pragma unroll
        for (int j = 0; j < TN; j++) acc[i][j] = 0.f;

    int ar = tid >> 2;            // 0..63
    int ak = (tid & 3) * 4;       // 0,4,8,12
    int bk = tid >> 4;            // 0..15
    int bc = (tid & 15) * 4;      // 0..60

    for (int k0 = 0; k0 < MDIM; k0 += BK) {
        float4 a0 = *(const float4*)(A + (size_t)(row0 + ar)      * MDIM + k0 + ak);
        float4 a1 = *(const float4*)(A + (size_t)(row0 + ar + 64) * MDIM + k0 + ak);
        As[ak + 0][ar] = a0.x; As[ak + 1][ar] = a0.y;
        As[ak + 2][ar] = a0.z; As[ak + 3][ar] = a0.w;
        As[ak + 0][ar + 64] = a1.x; As[ak + 1][ar + 64] = a1.y;
        As[ak + 2][ar + 64] = a1.z; As[ak + 3][ar + 64] = a1.w;

        float4 b0 = *(const float4*)(Bw + (size_t)(k0 + bk) * MDIM + col0 + bc);
        *(float4*)&Bs[bk][bc] = b0;
        __syncthreads();

#pragma unroll
        for (int kk = 0; kk < BK; kk++) {
            float4 av0 = *(float4*)&As[kk][ty * TM];
            float4 av1 = *(float4*)&As[kk][ty * TM + 4];
            float4 bv  = *(float4*)&Bs[kk][tx * TN];
            float a[TM] = {av0.x, av0.y, av0.z, av0.w, av1.x, av1.y, av1.z, av1.w};
            float b[TN] = {bv.x, bv.y, bv.z, bv.w};
#pragma unroll
            for (int i = 0; i < TM; i++)
#pragma unroll
                for (int j = 0; j < TN; j++)
                    acc[i][j] = fmaf(a[i], b[j], acc[i][j]);
        }
        __syncthreads();
    }

    float4 bb = *(const float4*)(bias + (size_t)e * MDIM + col0 + tx * TN);
#pragma unroll
    for (int i = 0; i < TM; i++) {
        int row = row0 + ty * TM + i;
        float4 o;
        o.x = acc[i][0] + bb.x;
        o.y = acc[i][1] + bb.y;
        o.z = acc[i][2] + bb.z;
        o.w = acc[i][3] + bb.w;
        *(float4*)(Cp + (size_t)row * MDIM + col0 + tx * TN) = o;
    }
}

// ---------------- combine: weighted scatter back to tokens ----------------
__global__ void k_combine(float* __restrict__ out) {
    int s = blockIdx.x;
    float w1 = g_w1[s], w2 = g_w2[s];
    int sl1 = g_slot1[s], sl2 = g_slot2[s];
    int i = threadIdx.x;   // 256 threads, MDIM/4 float4s
    float4 r = make_float4(0.f, 0.f, 0.f, 0.f);
    if (sl1 >= 0) {
        float4 v = ((const float4*)(g_eout + (size_t)sl1 * MDIM))[i];
        r.x += w1 * v.x; r.y += w1 * v.y; r.z += w1 * v.z; r.w += w1 * v.w;
    }
    if (sl2 >= 0) {
        float4 v = ((const float4*)(g_eout + (size_t)sl2 * MDIM))[i];
        r.x += w2 * v.x; r.y += w2 * v.y; r.z += w2 * v.z; r.w += w2 * v.w;
    }
    ((float4*)(out + (size_t)s * MDIM))[i] = r;
}

// ---------------- launch ----------------
extern "C" void kernel_launch(void* const* d_in, const int* in_sizes, int n_in,
                              void* d_out, int out_size) {
    const float* x  = (const float*)d_in[0];   // [2,2048,1024]
    const float* wg = (const float*)d_in[1];   // [1024,8]
    const float* ew = (const float*)d_in[2];   // [8,1024,1024]
    const float* eb = (const float*)d_in[3];   // [8,1024]
    float* out = (float*)d_out;

    k_init<<<(NSLOT + 255) / 256, 256>>>();
    k_gate<<<GATE_BLOCKS, 256>>>(x, wg);
    k_scan<<<1, 256>>>(out, out_size);
    k_gather<<<NSLOT, 256>>>(x);
    dim3 gg(MDIM / BN, CAP / BM, NEXP);   // 16 x 8 x 8
    k_gemm<<<gg, 256>>>(ew, eb);
    k_combine<<<S_TOK, 256>>>(out);
}

// round 4
// speedup vs baseline: 2.3160x; 2.3160x over previous
#include <cuda_runtime.h>
#include <math.h>
#include <stdint.h>

#define S_TOK 4096
#define MDIM  1024
#define NEXP  8
#define CAP   1024
#define NSLOT (NEXP*CAP)        // 8192
#define GATE_BLOCKS (S_TOK/8)   // 512

// ---------------- device scratch (no allocations allowed) ----------------
__device__ int   g_e1[S_TOK], g_e2[S_TOK];
__device__ float g_p1[S_TOK], g_p2[S_TOK];
__device__ float g_w1[S_TOK], g_w2[S_TOK];
__device__ int   g_slot1[S_TOK], g_slot2[S_TOK];
__device__ int   g_slot2tok[NSLOT];
__device__ float g_me_part[GATE_BLOCKS*NEXP];
__device__ int   g_ce_part[GATE_BLOCKS*NEXP];
__device__ float g_disp[(size_t)NSLOT*MDIM];     // 32 MB (tf32-rounded dispatched tokens)
__device__ float g_eout[(size_t)NSLOT*MDIM];     // 32 MB (expert outputs)

// ---------------- helpers ----------------
__device__ __forceinline__ uint32_t smem_u32(const void* p) {
    uint32_t a;
    asm("{ .reg .u64 t; cvta.to.shared.u64 t, %1; cvt.u32.u64 %0, t; }" : "=r"(a) : "l"(p));
    return a;
}
__device__ __forceinline__ float to_tf32(float v) {
    float r;
    asm("cvt.rna.tf32.f32 %0, %1;" : "=f"(r) : "f"(v));
    return r;
}
__device__ __forceinline__ uint32_t tf32_bits(float v) {
    float r;
    asm("cvt.rna.tf32.f32 %0, %1;" : "=f"(r) : "f"(v));
    return __float_as_uint(r);
}
__device__ __forceinline__ void mma_tf32(float* d, const uint32_t* a, const uint32_t* b) {
    asm volatile(
        "mma.sync.aligned.m16n8k8.row.col.f32.tf32.tf32.f32 "
        "{%0,%1,%2,%3}, {%4,%5,%6,%7}, {%8,%9}, {%0,%1,%2,%3};"
        : "+f"(d[0]), "+f"(d[1]), "+f"(d[2]), "+f"(d[3])
        : "r"(a[0]), "r"(a[1]), "r"(a[2]), "r"(a[3]), "r"(b[0]), "r"(b[1]));
}
#define CP_ASYNC16(dst, src) \
    asm volatile("cp.async.cg.shared.global [%0], [%1], 16;" :: "r"(dst), "l"(src))
#define CP_COMMIT() asm volatile("cp.async.commit_group;" ::: "memory")
#define CP_WAIT1()  asm volatile("cp.async.wait_group 1;" ::: "memory")
#define CP_WAIT0()  asm volatile("cp.async.wait_group 0;" ::: "memory")

// ---------------- init: reset slot->token map ----------------
__global__ void k_init() {
    int i = blockIdx.x * blockDim.x + threadIdx.x;
    if (i < NSLOT) g_slot2tok[i] = -1;
}

// ---------------- gating ----------------
__global__ void k_gate(const float* __restrict__ x, const float* __restrict__ wg) {
    int warp = threadIdx.x >> 5, lane = threadIdx.x & 31;
    int s = blockIdx.x * 8 + warp;

    float acc[NEXP];
#pragma unroll
    for (int e = 0; e < NEXP; e++) acc[e] = 0.f;

    const float* xr = x + (size_t)s * MDIM;
    for (int m = lane; m < MDIM; m += 32) {
        float xv = xr[m];
        const float4* w4 = (const float4*)(wg + (size_t)m * NEXP);
        float4 w0 = w4[0], w1 = w4[1];
        acc[0] += xv * w0.x; acc[1] += xv * w0.y;
        acc[2] += xv * w0.z; acc[3] += xv * w0.w;
        acc[4] += xv * w1.x; acc[5] += xv * w1.y;
        acc[6] += xv * w1.z; acc[7] += xv * w1.w;
    }
#pragma unroll
    for (int o = 16; o > 0; o >>= 1) {
#pragma unroll
        for (int e = 0; e < NEXP; e++)
            acc[e] += __shfl_down_sync(0xFFFFFFFFu, acc[e], o);
    }

    __shared__ float sh_g[8][NEXP];
    __shared__ int   sh_e1[8];

    if (lane == 0) {
        float mx = acc[0];
#pragma unroll
        for (int e = 1; e < NEXP; e++) mx = fmaxf(mx, acc[e]);
        float ex[NEXP]; float sum = 0.f;
#pragma unroll
        for (int e = 0; e < NEXP; e++) { ex[e] = expf(acc[e] - mx); sum += ex[e]; }
        float inv = 1.f / sum;

        int e1 = 0; float b1 = acc[0];
#pragma unroll
        for (int e = 1; e < NEXP; e++) if (acc[e] > b1) { b1 = acc[e]; e1 = e; }
        int e2 = -1; float b2 = -3.4e38f;
#pragma unroll
        for (int e = 0; e < NEXP; e++) if (e != e1 && acc[e] > b2) { b2 = acc[e]; e2 = e; }

        float p1 = 0.f, p2 = 0.f;
#pragma unroll
        for (int e = 0; e < NEXP; e++) {
            float ge = ex[e] * inv;
            if (e == e1) p1 = ge;
            if (e == e2) p2 = ge;
            sh_g[warp][e] = ge;
        }
        g_e1[s] = e1; g_e2[s] = e2;
        g_p1[s] = p1; g_p2[s] = p2;
        sh_e1[warp] = e1;
    }
    __syncthreads();

    if (threadIdx.x < NEXP) {
        int e = threadIdx.x;
        float ms = 0.f; int cs = 0;
#pragma unroll
        for (int w = 0; w < 8; w++) { ms += sh_g[w][e]; cs += (sh_e1[w] == e); }
        g_me_part[blockIdx.x * NEXP + e] = ms;
        g_ce_part[blockIdx.x * NEXP + e] = cs;
    }
}

// ---------------- scan ----------------
__global__ void k_scan(float* __restrict__ out, int out_size) {
    const int T = 256, PT = S_TOK / T;
    int tid = threadIdx.x;

    __shared__ int   sc1[T][NEXP], sc2[T][NEXP];
    __shared__ float sh_me[NEXP];
    __shared__ int   sh_ce[NEXP];
    __shared__ int   tot1[NEXP];

    if (tid < NEXP) {
        float ms = 0.f; int cs = 0;
        for (int b = 0; b < GATE_BLOCKS; b++) {
            ms += g_me_part[b * NEXP + tid];
            cs += g_ce_part[b * NEXP + tid];
        }
        sh_me[tid] = ms; sh_ce[tid] = cs;
    }

    int c1[NEXP], c2[NEXP];
#pragma unroll
    for (int e = 0; e < NEXP; e++) { c1[e] = 0; c2[e] = 0; }
    for (int i = 0; i < PT; i++) {
        int s = tid * PT + i;
        c1[g_e1[s]]++;
        c2[g_e2[s]]++;
    }
#pragma unroll
    for (int e = 0; e < NEXP; e++) { sc1[tid][e] = c1[e]; sc2[tid][e] = c2[e]; }
    __syncthreads();

    for (int off = 1; off < T; off *= 2) {
        int v1[NEXP], v2[NEXP];
        if (tid >= off) {
#pragma unroll
            for (int e = 0; e < NEXP; e++) { v1[e] = sc1[tid - off][e]; v2[e] = sc2[tid - off][e]; }
        }
        __syncthreads();
        if (tid >= off) {
#pragma unroll
            for (int e = 0; e < NEXP; e++) { sc1[tid][e] += v1[e]; sc2[tid][e] += v2[e]; }
        }
        __syncthreads();
    }
    if (tid < NEXP) tot1[tid] = sc1[T - 1][tid];

    int b1[NEXP], b2[NEXP];
#pragma unroll
    for (int e = 0; e < NEXP; e++) { b1[e] = sc1[tid][e] - c1[e]; b2[e] = sc2[tid][e] - c2[e]; }
    __syncthreads();

    for (int i = 0; i < PT; i++) {
        int s = tid * PT + i;
        int e1 = g_e1[s], e2 = g_e2[s];
        int loc1 = b1[e1]++;
        int loc2 = b2[e2]++ + tot1[e2];
        float p1 = g_p1[s], p2 = g_p2[s];
        bool k1 = (loc1 < CAP), k2 = (loc2 < CAP);
        float gg1 = k1 ? p1 : 0.f, gg2 = k2 ? p2 : 0.f;
        float den = gg1 + gg2;
        den = fmaxf(den, 1.1920929e-07f);
        g_w1[s] = gg1 / den;
        g_w2[s] = gg2 / den;
        int sl1 = k1 ? (e1 * CAP + loc1) : -1;
        int sl2 = k2 ? (e2 * CAP + loc2) : -1;
        g_slot1[s] = sl1; g_slot2[s] = sl2;
        if (sl1 >= 0) g_slot2tok[sl1] = s;
        if (sl2 >= 0) g_slot2tok[sl2] = s;
    }

    if (tid == 0 && out_size > S_TOK * MDIM) {
        float la = 0.f;
#pragma unroll
        for (int e = 0; e < NEXP; e++)
            la += (sh_me[e] / (float)S_TOK) * ((float)sh_ce[e] / (float)S_TOK);
        out[(size_t)S_TOK * MDIM] = la * (float)NEXP;
    }
}

// ---------------- gather: per-expert token buffers, pre-rounded to tf32 ----------------
__global__ void k_gather(const float* __restrict__ x) {
    int slot = blockIdx.x;
    int t = g_slot2tok[slot];
    float4* dst = (float4*)(g_disp + (size_t)slot * MDIM);
    int i = threadIdx.x;   // 256 threads, MDIM/4 = 256
    if (t < 0) {
        dst[i] = make_float4(0.f, 0.f, 0.f, 0.f);
    } else {
        float4 v = ((const float4*)(x + (size_t)t * MDIM))[i];
        v.x = to_tf32(v.x); v.y = to_tf32(v.y);
        v.z = to_tf32(v.z); v.w = to_tf32(v.w);
        dst[i] = v;
    }
}

// ---------------- tensor-core GEMM via mma.sync tf32 ----------------
// CTA tile 128x128x16, 8 warps (warp tile 32x64), double-buffered cp.async
#define BM 128
#define BN 128
#define BK 16
#define NSTG (MDIM / BK)            // 64
#define ASTRIDE 20                  // 16 + 4 pad: banks (r*20+k)%32 distinct for r=0..7
#define BSTRIDE 136                 // 128 + 8 pad: banks (k*136+n)%32 distinct for k groups
#define ABUF (BM * ASTRIDE)         // 2560 floats
#define BBUF (BK * BSTRIDE)         // 2176 floats
#define BUFSZ (ABUF + BBUF)         // 4736 floats
#define GEMM_SMEM (2 * BUFSZ * 4)   // 37888 bytes < 48K

__global__ void __launch_bounds__(256, 2) k_gemm_mma(const float* __restrict__ W,
                                                     const float* __restrict__ bias) {
    extern __shared__ float smf[];
    int tid = threadIdx.x, wid = tid >> 5, lane = tid & 31;
    int grp = lane >> 2, tg = lane & 3;
    int e = blockIdx.z;
    int row0 = blockIdx.y * BM;
    int col0 = blockIdx.x * BN;
    const float* Ag = g_disp + (size_t)e * CAP * MDIM + (size_t)row0 * MDIM;
    const float* Bg = W + (size_t)e * MDIM * MDIM + col0;
    int wm = (wid & 3) * 32, wn = (wid >> 2) * 64;

    // bias segments for this thread's output columns
    float2 bb[8];
#pragma unroll
    for (int nj = 0; nj < 8; nj++)
        bb[nj] = *(const float2*)(bias + (size_t)e * MDIM + col0 + wn + nj * 8 + tg * 2);

    float d[2][8][4];
#pragma unroll
    for (int mi = 0; mi < 2; mi++)
#pragma unroll
        for (int nj = 0; nj < 8; nj++)
#pragma unroll
            for (int q = 0; q < 4; q++) d[mi][nj][q] = 0.f;

    // cp.async addressing (per thread: 2 A chunks + 2 B chunks of 16B)
    int arow = tid >> 2, aq = tid & 3;     // A rows arow, arow+64 ; 16B chunk aq
    int brow = tid >> 5, bq = tid & 31;    // B k-rows brow, brow+8 ; 16B chunk bq
    uint32_t s0 = smem_u32(smf);

#define LOAD_STAGE(buf, k0) do {                                                       \
    uint32_t sa = s0 + (uint32_t)((buf) * BUFSZ) * 4u;                                 \
    uint32_t sb_ = sa + ABUF * 4u;                                                     \
    CP_ASYNC16(sa + (uint32_t)(arow * ASTRIDE + aq * 4) * 4u,                          \
               Ag + (size_t)arow * MDIM + (k0) + aq * 4);                              \
    CP_ASYNC16(sa + (uint32_t)((arow + 64) * ASTRIDE + aq * 4) * 4u,                   \
               Ag + (size_t)(arow + 64) * MDIM + (k0) + aq * 4);                       \
    CP_ASYNC16(sb_ + (uint32_t)(brow * BSTRIDE + bq * 4) * 4u,                         \
               Bg + (size_t)((k0) + brow) * MDIM + bq * 4);                            \
    CP_ASYNC16(sb_ + (uint32_t)((brow + 8) * BSTRIDE + bq * 4) * 4u,                   \
               Bg + (size_t)((k0) + brow + 8) * MDIM + bq * 4);                        \
} while (0)

    LOAD_STAGE(0, 0);
    CP_COMMIT();

    for (int s = 0; s < NSTG; s++) {
        int cur = s & 1;
        if (s + 1 < NSTG) {
            LOAD_STAGE(cur ^ 1, (s + 1) * BK);
            CP_COMMIT();
            CP_WAIT1();
        } else {
            CP_WAIT0();
        }
        __syncthreads();

        const float* As = smf + cur * BUFSZ;
        const float* Bs = As + ABUF;
#pragma unroll
        for (int ks = 0; ks < 2; ks++) {
            int kb = ks * 8;
            uint32_t a[2][4];
#pragma unroll
            for (int mi = 0; mi < 2; mi++) {
                const float* ap = As + (wm + mi * 16 + grp) * ASTRIDE + kb + tg;
                a[mi][0] = __float_as_uint(ap[0]);                 // already tf32-rounded
                a[mi][1] = __float_as_uint(ap[8 * ASTRIDE]);
                a[mi][2] = __float_as_uint(ap[4]);
                a[mi][3] = __float_as_uint(ap[8 * ASTRIDE + 4]);
            }
            uint32_t b[8][2];
#pragma unroll
            for (int nj = 0; nj < 8; nj++) {
                const float* bp = Bs + (kb + tg) * BSTRIDE + wn + nj * 8 + grp;
                b[nj][0] = tf32_bits(bp[0]);
                b[nj][1] = tf32_bits(bp[4 * BSTRIDE]);
            }
#pragma unroll
            for (int mi = 0; mi < 2; mi++)
#pragma unroll
                for (int nj = 0; nj < 8; nj++)
                    mma_tf32(d[mi][nj], a[mi], b[nj]);
        }
        __syncthreads();
    }

    // epilogue: write 32x64 warp tile + bias
    float* Cp = g_eout + (size_t)e * CAP * MDIM;
#pragma unroll
    for (int mi = 0; mi < 2; mi++) {
        int row = row0 + wm + mi * 16 + grp;
#pragma unroll
        for (int nj = 0; nj < 8; nj++) {
            int col = col0 + wn + nj * 8 + tg * 2;
            float2 v0, v1;
            v0.x = d[mi][nj][0] + bb[nj].x;
            v0.y = d[mi][nj][1] + bb[nj].y;
            v1.x = d[mi][nj][2] + bb[nj].x;
            v1.y = d[mi][nj][3] + bb[nj].y;
            *(float2*)(Cp + (size_t)row * MDIM + col) = v0;
            *(float2*)(Cp + (size_t)(row + 8) * MDIM + col) = v1;
        }
    }
}

// ---------------- combine ----------------
__global__ void k_combine(float* __restrict__ out) {
    int s = blockIdx.x;
    float w1 = g_w1[s], w2 = g_w2[s];
    int sl1 = g_slot1[s], sl2 = g_slot2[s];
    int i = threadIdx.x;
    float4 r = make_float4(0.f, 0.f, 0.f, 0.f);
    if (sl1 >= 0) {
        float4 v = ((const float4*)(g_eout + (size_t)sl1 * MDIM))[i];
        r.x += w1 * v.x; r.y += w1 * v.y; r.z += w1 * v.z; r.w += w1 * v.w;
    }
    if (sl2 >= 0) {
        float4 v = ((const float4*)(g_eout + (size_t)sl2 * MDIM))[i];
        r.x += w2 * v.x; r.y += w2 * v.y; r.z += w2 * v.z; r.w += w2 * v.w;
    }
    ((float4*)(out + (size_t)s * MDIM))[i] = r;
}

// ---------------- launch ----------------
extern "C" void kernel_launch(void* const* d_in, const int* in_sizes, int n_in,
                              void* d_out, int out_size) {
    const float* x  = (const float*)d_in[0];   // [2,2048,1024]
    const float* wg = (const float*)d_in[1];   // [1024,8]
    const float* ew = (const float*)d_in[2];   // [8,1024,1024]
    const float* eb = (const float*)d_in[3];   // [8,1024]
    float* out = (float*)d_out;

    k_init<<<(NSLOT + 255) / 256, 256>>>();
    k_gate<<<GATE_BLOCKS, 256>>>(x, wg);
    k_scan<<<1, 256>>>(out, out_size);
    k_gather<<<NSLOT, 256>>>(x);
    dim3 gg(MDIM / BN, CAP / BM, NEXP);   // 8 x 8 x 8
    k_gemm_mma<<<gg, 256, GEMM_SMEM>>>(ew, eb);
    k_combine<<<S_TOK, 256>>>(out);
}